// round 3
// baseline (speedup 1.0000x reference)
#include <cuda_runtime.h>
#include <cstdint>

// MultiHeadAttentionMap: B=2, H=16, S=2048, D=1024, hd=64
// Round 2: TF32 mma.sync flash attention + proj GEMM, fragments via ldmatrix.x4
// (b16 ldmatrix trick for tf32), V/W transposed+swizzled in smem for B-frags.

#define S_LEN  2048
#define DMODEL 1024
#define HDIM   64
#define PAD    68                       // words per row for sQ/sP/sK/sA (row stride 272B = 17*16B)
#define ATTN_SMEM_WORDS (2 * 64 * PAD + 64 * 64)   // sQ/sP, sK, sVT
#define ATTN_SMEM_BYTES (ATTN_SMEM_WORDS * 4)

__device__ float g_attn[2u * S_LEN * DMODEL]; // 16 MB scratch

__device__ __forceinline__ uint32_t f2tf(float x) {
    uint32_t r;
    asm("cvt.rna.tf32.f32 %0, %1;" : "=r"(r) : "f"(x));
    return r;
}

__device__ __forceinline__ void mma_tf32(float c[4], const uint32_t a[4],
                                         uint32_t b0, uint32_t b1) {
    asm volatile(
        "mma.sync.aligned.m16n8k8.row.col.f32.tf32.tf32.f32 "
        "{%0,%1,%2,%3}, {%4,%5,%6,%7}, {%8,%9}, {%0,%1,%2,%3};\n"
        : "+f"(c[0]), "+f"(c[1]), "+f"(c[2]), "+f"(c[3])
        : "r"(a[0]), "r"(a[1]), "r"(a[2]), "r"(a[3]), "r"(b0), "r"(b1));
}

__device__ __forceinline__ void ldsm4(uint32_t& r0, uint32_t& r1, uint32_t& r2,
                                      uint32_t& r3, uint32_t saddr) {
    asm volatile("ldmatrix.sync.aligned.m8n8.x4.shared.b16 {%0,%1,%2,%3}, [%4];"
                 : "=r"(r0), "=r"(r1), "=r"(r2), "=r"(r3) : "r"(saddr));
}

// swizzled word index into a [64 rows][64 words] tile (transposed operand)
__device__ __forceinline__ int vt_word(int row, int k) {
    int u = (k >> 2) ^ ((row + (row >> 3)) & 7);
    return row * 64 + (u << 2) + (k & 3);
}

// ---------------------------------------------------------------------------
// Flash attention: CTA = (b, 64-query tile, h). 4 warps x 16 query rows.
// grid = (2, 32, 16)  [b fastest: both batches share bias tiles in L2]
// ---------------------------------------------------------------------------
__global__ void __launch_bounds__(128)
flash_attn_tf32_kernel(const float* __restrict__ Q, const float* __restrict__ K,
                       const float* __restrict__ V, const float* __restrict__ Bias) {
    extern __shared__ uint32_t sm[];
    uint32_t* sQ  = sm;                 // [64][PAD]; dead after prologue -> reused as sP
    uint32_t* sK  = sm + 64 * PAD;      // [64][PAD]
    uint32_t* sVT = sm + 2 * 64 * PAD;  // [64 d][64 k] swizzled (V transposed)
    const uint32_t smem_u32 = (uint32_t)__cvta_generic_to_shared(sm);
    const uint32_t sP_b  = smem_u32;
    const uint32_t sK_b  = smem_u32 + 64 * PAD * 4;
    const uint32_t sVT_b = smem_u32 + 2 * 64 * PAD * 4;

    const int b  = blockIdx.x;
    const int q0 = blockIdx.y * 64;
    const int h  = blockIdx.z;

    const int tid  = threadIdx.x;
    const int w    = tid >> 5;
    const int lane = tid & 31;
    const int g    = lane >> 2;    // fragment row-in-8
    const int t    = lane & 3;     // fragment col quad
    const int e    = lane & 7;     // ldmatrix row lane
    const int qq   = lane >> 3;    // ldmatrix tile select (0..3)
    const int q01  = qq & 1;
    const int q23  = qq >> 1;
    const int wr   = w * 16;

    // ldmatrix address base for A-style frags in sP/sQ (per ks: +ks*32 bytes)
    const uint32_t aAddrBase = sP_b + (uint32_t)(wr + (q01 << 3) + e) * PAD * 4 + (q23 << 4);

    const size_t bh_off = (size_t)b * S_LEN * DMODEL + (size_t)h * HDIM;
    const float* Qb = Q + bh_off + (size_t)q0 * DMODEL;
    const float* Kb = K + bh_off;
    const float* Vb = V + bh_off;
    const float* Bb = Bias + ((size_t)h * S_LEN + q0) * S_LEN;

    // Load Q tile [64 x 64] -> tf32 smem (row-major, PAD)
    for (int i = tid; i < 64 * 16; i += 128) {
        int r = i >> 4, c = (i & 15) << 2;
        float4 v = *(const float4*)(Qb + (size_t)r * DMODEL + c);
        uint32_t* d = sQ + r * PAD + c;
        d[0] = f2tf(v.x); d[1] = f2tf(v.y); d[2] = f2tf(v.z); d[3] = f2tf(v.w);
    }
    __syncthreads();

    // Hoist Q A-fragments via ldmatrix (sQ dead afterwards -> becomes sP)
    uint32_t aQ[8][4];
    #pragma unroll
    for (int ks = 0; ks < 8; ks++)
        ldsm4(aQ[ks][0], aQ[ks][1], aQ[ks][2], aQ[ks][3], aAddrBase + ks * 32);

    float m0 = -1e30f, m1 = -1e30f, l0 = 0.f, l1 = 0.f;
    float O[8][4];
    #pragma unroll
    for (int n = 0; n < 8; n++) { O[n][0] = 0.f; O[n][1] = 0.f; O[n][2] = 0.f; O[n][3] = 0.f; }

    for (int kt = 0; kt < 32; kt++) {
        const int kn0 = kt * 64;
        __syncthreads();  // aQ hoist done (kt=0) / prior PV done with sK,sVT
        for (int i = tid; i < 64 * 16; i += 128) {
            int r = i >> 4, c = (i & 15) << 2;
            const size_t go = (size_t)(kn0 + r) * DMODEL + c;
            float4 kv = *(const float4*)(Kb + go);
            float4 vv = *(const float4*)(Vb + go);
            uint32_t* dk = sK + r * PAD + c;
            dk[0] = f2tf(kv.x); dk[1] = f2tf(kv.y); dk[2] = f2tf(kv.z); dk[3] = f2tf(kv.w);
            // V transposed + swizzled: sVT[d][k]
            sVT[vt_word(c + 0, r)] = f2tf(vv.x);
            sVT[vt_word(c + 1, r)] = f2tf(vv.y);
            sVT[vt_word(c + 2, r)] = f2tf(vv.z);
            sVT[vt_word(c + 3, r)] = f2tf(vv.w);
        }
        __syncthreads();

        // S = Q K^T : 8 n-tiles, K=64 in 8 steps (B frags via ldmatrix.x4, 2 ks per ldsm)
        float Sf[8][4];
        #pragma unroll
        for (int n = 0; n < 8; n++) {
            Sf[n][0] = 0.f; Sf[n][1] = 0.f; Sf[n][2] = 0.f; Sf[n][3] = 0.f;
            const uint32_t knb = sK_b + (uint32_t)(n * 8 + e) * PAD * 4 + (qq << 4);
            #pragma unroll
            for (int ksp = 0; ksp < 4; ksp++) {
                uint32_t b0, b1, b2, b3;
                ldsm4(b0, b1, b2, b3, knb + ksp * 64);
                mma_tf32(Sf[n], aQ[2 * ksp],     b0, b1);
                mma_tf32(Sf[n], aQ[2 * ksp + 1], b2, b3);
            }
        }

        // bias + scale ((S + bias) * 0.125), online softmax
        const float* Br0 = Bb + (size_t)(wr + g)     * S_LEN + kn0 + 2 * t;
        const float* Br1 = Bb + (size_t)(wr + g + 8) * S_LEN + kn0 + 2 * t;
        float rm0 = -1e30f, rm1 = -1e30f;
        #pragma unroll
        for (int n = 0; n < 8; n++) {
            float2 b0v = *(const float2*)(Br0 + n * 8);
            float2 b1v = *(const float2*)(Br1 + n * 8);
            Sf[n][0] = (Sf[n][0] + b0v.x) * 0.125f;
            Sf[n][1] = (Sf[n][1] + b0v.y) * 0.125f;
            Sf[n][2] = (Sf[n][2] + b1v.x) * 0.125f;
            Sf[n][3] = (Sf[n][3] + b1v.y) * 0.125f;
            rm0 = fmaxf(rm0, fmaxf(Sf[n][0], Sf[n][1]));
            rm1 = fmaxf(rm1, fmaxf(Sf[n][2], Sf[n][3]));
        }
        rm0 = fmaxf(rm0, __shfl_xor_sync(0xffffffffu, rm0, 1));
        rm0 = fmaxf(rm0, __shfl_xor_sync(0xffffffffu, rm0, 2));
        rm1 = fmaxf(rm1, __shfl_xor_sync(0xffffffffu, rm1, 1));
        rm1 = fmaxf(rm1, __shfl_xor_sync(0xffffffffu, rm1, 2));

        float mn0 = fmaxf(m0, rm0), mn1 = fmaxf(m1, rm1);
        float al0 = __expf(m0 - mn0), al1 = __expf(m1 - mn1);
        float rs0 = 0.f, rs1 = 0.f;
        uint32_t* sP = sQ;
        #pragma unroll
        for (int n = 0; n < 8; n++) {
            float p00 = __expf(Sf[n][0] - mn0);
            float p01 = __expf(Sf[n][1] - mn0);
            float p10 = __expf(Sf[n][2] - mn1);
            float p11 = __expf(Sf[n][3] - mn1);
            rs0 += p00 + p01;
            rs1 += p10 + p11;
            *(uint2*)(sP + (wr + g)     * PAD + n * 8 + 2 * t) = make_uint2(f2tf(p00), f2tf(p01));
            *(uint2*)(sP + (wr + g + 8) * PAD + n * 8 + 2 * t) = make_uint2(f2tf(p10), f2tf(p11));
        }
        rs0 += __shfl_xor_sync(0xffffffffu, rs0, 1);
        rs0 += __shfl_xor_sync(0xffffffffu, rs0, 2);
        rs1 += __shfl_xor_sync(0xffffffffu, rs1, 1);
        rs1 += __shfl_xor_sync(0xffffffffu, rs1, 2);

        m0 = mn0; m1 = mn1;
        l0 = l0 * al0 + rs0;
        l1 = l1 * al1 + rs1;
        #pragma unroll
        for (int n = 0; n < 8; n++) {
            O[n][0] *= al0; O[n][1] *= al0; O[n][2] *= al1; O[n][3] *= al1;
        }
        __syncwarp();  // sP rows [wr, wr+16) are warp-private

        // O += P V : aP via ldmatrix from sP, V frags via ldmatrix from sVT
        #pragma unroll
        for (int ks = 0; ks < 8; ks++) {
            uint32_t aP[4];
            ldsm4(aP[0], aP[1], aP[2], aP[3], aAddrBase + ks * 32);
            #pragma unroll
            for (int np = 0; np < 4; np++) {
                const int d   = (2 * np + q23) * 8 + e;
                const int key = (d + (d >> 3)) & 7;
                const int u2  = (ks * 2 + q01) ^ key;
                uint32_t v0, v1, v2, v3;
                ldsm4(v0, v1, v2, v3, sVT_b + (uint32_t)d * 256 + (uint32_t)u2 * 16);
                mma_tf32(O[2 * np],     aP, v0, v1);
                mma_tf32(O[2 * np + 1], aP, v2, v3);
            }
        }
    }

    const float inv0 = 1.0f / l0;
    const float inv1 = 1.0f / l1;
    float* o0 = g_attn + bh_off + (size_t)(q0 + wr + g)     * DMODEL;
    float* o1 = g_attn + bh_off + (size_t)(q0 + wr + g + 8) * DMODEL;
    #pragma unroll
    for (int n = 0; n < 8; n++) {
        *(float2*)(o0 + n * 8 + 2 * t) = make_float2(O[n][0] * inv0, O[n][1] * inv0);
        *(float2*)(o1 + n * 8 + 2 * t) = make_float2(O[n][2] * inv1, O[n][3] * inv1);
    }
}

// ---------------------------------------------------------------------------
// Projection: out[4096,1024] = g_attn @ w_out[1024,1024], TF32 + ldmatrix.
// grid = (16, 64), 128 threads, 64x64 CTA tile, K chunks of 64.
// ---------------------------------------------------------------------------
__global__ void __launch_bounds__(128)
proj_tf32_kernel(const float* __restrict__ W, float* __restrict__ out) {
    __shared__ uint32_t sA[64 * PAD];   // [m][k] row-major
    __shared__ uint32_t sBT[64 * 64];   // [n][k] transposed W, swizzled

    const int n0 = blockIdx.x * 64;
    const int m0 = blockIdx.y * 64;
    const int tid  = threadIdx.x;
    const int w    = tid >> 5;
    const int lane = tid & 31;
    const int g    = lane >> 2;
    const int t    = lane & 3;
    const int e    = lane & 7;
    const int qq   = lane >> 3;
    const int q01  = qq & 1;
    const int q23  = qq >> 1;
    const int wr   = w * 16;

    const uint32_t sA_b  = (uint32_t)__cvta_generic_to_shared(sA);
    const uint32_t sBT_b = (uint32_t)__cvta_generic_to_shared(sBT);
    const uint32_t aAddrBase = sA_b + (uint32_t)(wr + (q01 << 3) + e) * PAD * 4 + (q23 << 4);

    float O[8][4];
    #pragma unroll
    for (int n = 0; n < 8; n++) { O[n][0] = 0.f; O[n][1] = 0.f; O[n][2] = 0.f; O[n][3] = 0.f; }

    for (int kc = 0; kc < 16; kc++) {
        __syncthreads();
        for (int i = tid; i < 64 * 16; i += 128) {
            int r = i >> 4, c = (i & 15) << 2;
            float4 av = *(const float4*)(g_attn + (size_t)(m0 + r) * DMODEL + kc * 64 + c);
            float4 bv = *(const float4*)(W + (size_t)(kc * 64 + r) * DMODEL + n0 + c);
            uint32_t* da = sA + r * PAD + c;
            da[0] = f2tf(av.x); da[1] = f2tf(av.y); da[2] = f2tf(av.z); da[3] = f2tf(av.w);
            sBT[vt_word(c + 0, r)] = f2tf(bv.x);
            sBT[vt_word(c + 1, r)] = f2tf(bv.y);
            sBT[vt_word(c + 2, r)] = f2tf(bv.z);
            sBT[vt_word(c + 3, r)] = f2tf(bv.w);
        }
        __syncthreads();
        #pragma unroll
        for (int ks = 0; ks < 8; ks++) {
            uint32_t aA[4];
            ldsm4(aA[0], aA[1], aA[2], aA[3], aAddrBase + ks * 32);
            #pragma unroll
            for (int np = 0; np < 4; np++) {
                const int d   = (2 * np + q23) * 8 + e;
                const int key = (d + (d >> 3)) & 7;
                const int u2  = (ks * 2 + q01) ^ key;
                uint32_t v0, v1, v2, v3;
                ldsm4(v0, v1, v2, v3, sBT_b + (uint32_t)d * 256 + (uint32_t)u2 * 16);
                mma_tf32(O[2 * np],     aA, v0, v1);
                mma_tf32(O[2 * np + 1], aA, v2, v3);
            }
        }
    }

    float* o0 = out + (size_t)(m0 + wr + g)     * DMODEL + n0;
    float* o1 = out + (size_t)(m0 + wr + g + 8) * DMODEL + n0;
    #pragma unroll
    for (int n = 0; n < 8; n++) {
        *(float2*)(o0 + n * 8 + 2 * t) = make_float2(O[n][0], O[n][1]);
        *(float2*)(o1 + n * 8 + 2 * t) = make_float2(O[n][2], O[n][3]);
    }
}

extern "C" void kernel_launch(void* const* d_in, const int* in_sizes, int n_in,
                              void* d_out, int out_size) {
    (void)in_sizes; (void)n_in; (void)out_size;
    const float* Q    = (const float*)d_in[0];
    const float* K    = (const float*)d_in[1];
    const float* V    = (const float*)d_in[2];
    const float* Bias = (const float*)d_in[3];
    const float* W    = (const float*)d_in[4];
    float* out = (float*)d_out;

    cudaFuncSetAttribute(flash_attn_tf32_kernel,
                         cudaFuncAttributeMaxDynamicSharedMemorySize, ATTN_SMEM_BYTES);
    flash_attn_tf32_kernel<<<dim3(2, 32, 16), 128, ATTN_SMEM_BYTES>>>(Q, K, V, Bias);
    proj_tf32_kernel<<<dim3(16, 64), 128>>>(W, out);
}